// round 5
// baseline (speedup 1.0000x reference)
#include <cuda_runtime.h>
#include <cstdint>

#define NN 50000
#define NE 800000
#define D  128

// Scratch (device globals — no allocations allowed)
__device__ float g_agg[(size_t)NN * D];   // per-layer aggregation buffer
__device__ float g_h1[(size_t)NN * D];    // layer-1 output
__device__ float g_h2[(size_t)NN * D];    // layer-2 output
__device__ float g_degf[NN];              // in-degree (as float)
__device__ int   g_is64;                  // 1 if edge_index is int64, 0 if int32

// ---------------------------------------------------------------------------
// Detect index dtype: if int64 (little-endian), the high 32-bit words of the
// first 64 entries are all zero (values in [0, 50000)). If int32, those words
// are real random indices — essentially never all zero.
__global__ void k_detect(const int* __restrict__ ei32) {
    if (blockIdx.x == 0 && threadIdx.x == 0) {
        int any = 0;
        #pragma unroll
        for (int i = 1; i < 128; i += 2) any |= ei32[i];
        g_is64 = (any == 0) ? 1 : 0;
    }
}

__device__ __forceinline__ int load_idx(const void* ei, long long pos) {
    if (g_is64) return (int)((const long long*)ei)[pos];
    return ((const int*)ei)[pos];
}

__global__ void k_zero_deg() {
    int i = blockIdx.x * blockDim.x + threadIdx.x;
    if (i < NN) g_degf[i] = 0.0f;
}

__global__ void k_deg(const void* __restrict__ ei) {
    int e = blockIdx.x * blockDim.x + threadIdx.x;
    if (e < NE) atomicAdd(&g_degf[load_idx(ei, (long long)NE + e)], 1.0f);
}

__global__ void k_zero_agg() {
    int i = blockIdx.x * blockDim.x + threadIdx.x;
    if (i < NN * D / 4)
        reinterpret_cast<float4*>(g_agg)[i] = make_float4(0.f, 0.f, 0.f, 0.f);
}

// One warp per edge: gather h[src] row (512B), reduce-add into agg[dst].
__global__ void k_scatter(const void* __restrict__ ei,
                          const float* __restrict__ h) {
    int w = (blockIdx.x * blockDim.x + threadIdx.x) >> 5;
    if (w >= NE) return;
    int lane = threadIdx.x & 31;
    int src = load_idx(ei, w);
    int dst = load_idx(ei, (long long)NE + w);
    float4 v = __ldg(reinterpret_cast<const float4*>(h + (size_t)src * D) + lane);
    float* ap = g_agg + (size_t)dst * D + (size_t)lane * 4;
    asm volatile("red.global.add.v4.f32 [%0], {%1, %2, %3, %4};"
                 :: "l"(ap), "f"(v.x), "f"(v.y), "f"(v.z), "f"(v.w)
                 : "memory");
}

// out[i,:] = (agg[i,:] - deg[i]*h[i,:]) @ W^T + deg[i]*b
// Tile: 128 rows x 128 cols (BN = full D_out), BK=16, 256 threads, 8x8 micro-tile.
__global__ __launch_bounds__(256)
void k_gemm(const float* __restrict__ h,
            const float* __restrict__ W,      // [D_out, D_in] row-major
            const float* __restrict__ bias,   // [D_out]
            float* __restrict__ out) {
    __shared__ float As[16][128];   // As[k][row] = agg - deg*h
    __shared__ float Bs[16][128];   // Bs[k][n]   = W[n][k]

    const int tid  = threadIdx.x;
    const int row0 = blockIdx.x * 128;
    const int tx   = tid & 15;      // col group
    const int ty   = tid >> 4;      // row group

    float acc[8][8];
    #pragma unroll
    for (int i = 0; i < 8; i++)
        #pragma unroll
        for (int j = 0; j < 8; j++) acc[i][j] = 0.0f;

    for (int k0 = 0; k0 < D; k0 += 16) {
        // ---- load A tile (with fused agg - deg*h) ----
        #pragma unroll
        for (int it = 0; it < 2; it++) {
            int idx = tid + it * 256;
            int r   = idx >> 2;            // 0..127
            int kq  = (idx & 3) * 4;       // 0,4,8,12
            int grow = row0 + r;
            float4 v = make_float4(0.f, 0.f, 0.f, 0.f);
            if (grow < NN) {
                float dg = g_degf[grow];
                float4 a4 = *reinterpret_cast<const float4*>(
                    g_agg + (size_t)grow * D + k0 + kq);
                float4 h4 = __ldg(reinterpret_cast<const float4*>(
                    h + (size_t)grow * D + k0 + kq));
                v = make_float4(a4.x - dg * h4.x, a4.y - dg * h4.y,
                                a4.z - dg * h4.z, a4.w - dg * h4.w);
            }
            As[kq + 0][r] = v.x;
            As[kq + 1][r] = v.y;
            As[kq + 2][r] = v.z;
            As[kq + 3][r] = v.w;
        }
        // ---- load B tile (transpose W on the fly) ----
        #pragma unroll
        for (int it = 0; it < 2; it++) {
            int idx = tid + it * 256;
            int n   = idx >> 2;            // 0..127
            int kq  = (idx & 3) * 4;
            float4 wv = __ldg(reinterpret_cast<const float4*>(
                W + (size_t)n * D + k0 + kq));
            Bs[kq + 0][n] = wv.x;
            Bs[kq + 1][n] = wv.y;
            Bs[kq + 2][n] = wv.z;
            Bs[kq + 3][n] = wv.w;
        }
        __syncthreads();

        #pragma unroll
        for (int kk = 0; kk < 16; kk++) {
            float a[8], bb[8];
            *reinterpret_cast<float4*>(a)      = *reinterpret_cast<const float4*>(&As[kk][ty * 8]);
            *reinterpret_cast<float4*>(a + 4)  = *reinterpret_cast<const float4*>(&As[kk][ty * 8 + 4]);
            *reinterpret_cast<float4*>(bb)     = *reinterpret_cast<const float4*>(&Bs[kk][tx * 8]);
            *reinterpret_cast<float4*>(bb + 4) = *reinterpret_cast<const float4*>(&Bs[kk][tx * 8 + 4]);
            #pragma unroll
            for (int i = 0; i < 8; i++)
                #pragma unroll
                for (int j = 0; j < 8; j++)
                    acc[i][j] += a[i] * bb[j];
        }
        __syncthreads();
    }

    // ---- epilogue: + deg[i]*b[n] ----
    #pragma unroll
    for (int i = 0; i < 8; i++) {
        int grow = row0 + ty * 8 + i;
        if (grow >= NN) continue;
        float dg = g_degf[grow];
        #pragma unroll
        for (int j = 0; j < 8; j += 4) {
            int col = tx * 8 + j;
            float4 o;
            o.x = acc[i][j + 0] + dg * __ldg(bias + col + 0);
            o.y = acc[i][j + 1] + dg * __ldg(bias + col + 1);
            o.z = acc[i][j + 2] + dg * __ldg(bias + col + 2);
            o.w = acc[i][j + 3] + dg * __ldg(bias + col + 3);
            *reinterpret_cast<float4*>(out + (size_t)grow * D + col) = o;
        }
    }
}

// ---------------------------------------------------------------------------
extern "C" void kernel_launch(void* const* d_in, const int* in_sizes, int n_in,
                              void* d_out, int out_size) {
    const float* x  = (const float*)d_in[0];
    const float* W1 = (const float*)d_in[1];
    const float* b1 = (const float*)d_in[2];
    const float* W2 = (const float*)d_in[3];
    const float* b2 = (const float*)d_in[4];
    const float* W3 = (const float*)d_in[5];
    const float* b3 = (const float*)d_in[6];
    const void*  ei = d_in[7];
    float* out = (float*)d_out;

    float *h1, *h2;
    cudaGetSymbolAddress((void**)&h1, g_h1);
    cudaGetSymbolAddress((void**)&h2, g_h2);

    const int ZB = 256;
    k_detect<<<1, 32>>>((const int*)ei);

    // degree (same edge_index for all 3 layers)
    k_zero_deg<<<(NN + ZB - 1) / ZB, ZB>>>();
    k_deg<<<(NE + ZB - 1) / ZB, ZB>>>(ei);

    const int scatter_blocks = (NE * 32 + 255) / 256;   // 1 warp per edge
    const int agg_blocks     = (NN * D / 4 + ZB - 1) / ZB;
    const int gemm_blocks    = (NN + 127) / 128;

    // layer 1: h1 = (agg(x) - deg*x) W1^T + deg*b1
    k_zero_agg<<<agg_blocks, ZB>>>();
    k_scatter<<<scatter_blocks, 256>>>(ei, x);
    k_gemm<<<gemm_blocks, 256>>>(x, W1, b1, h1);

    // layer 2
    k_zero_agg<<<agg_blocks, ZB>>>();
    k_scatter<<<scatter_blocks, 256>>>(ei, h1);
    k_gemm<<<gemm_blocks, 256>>>(h1, W2, b2, h2);

    // layer 3 -> d_out
    k_zero_agg<<<agg_blocks, ZB>>>();
    k_scatter<<<scatter_blocks, 256>>>(ei, h2);
    k_gemm<<<gemm_blocks, 256>>>(h2, W3, b3, out);
}

// round 6
// speedup vs baseline: 1.0045x; 1.0045x over previous
#include <cuda_runtime.h>
#include <cstdint>

#define NN 50000
#define NE 800000
#define D  128

// Scratch (device globals — no allocations allowed)
__device__ float g_agg[(size_t)NN * D];   // per-layer aggregation buffer
__device__ float g_h1[(size_t)NN * D];    // layer-1 output
__device__ float g_h2[(size_t)NN * D];    // layer-2 output
__device__ float g_degf[NN];              // in-degree (as float)
__device__ int   g_is64;                  // 1 if edge_index is int64, 0 if int32

// ---------------------------------------------------------------------------
// Detect index dtype: if int64 (little-endian), the high 32-bit words of the
// first 64 entries are all zero (values in [0, 50000)). If int32, those words
// are real random indices — essentially never all zero.
__global__ void k_detect(const int* __restrict__ ei32) {
    if (blockIdx.x == 0 && threadIdx.x == 0) {
        int any = 0;
        #pragma unroll
        for (int i = 1; i < 128; i += 2) any |= ei32[i];
        g_is64 = (any == 0) ? 1 : 0;
    }
}

__device__ __forceinline__ int load_idx(const void* ei, long long pos) {
    if (g_is64) return (int)((const long long*)ei)[pos];
    return ((const int*)ei)[pos];
}

__global__ void k_zero_deg() {
    int i = blockIdx.x * blockDim.x + threadIdx.x;
    if (i < NN) g_degf[i] = 0.0f;
}

__global__ void k_deg(const void* __restrict__ ei) {
    int e = blockIdx.x * blockDim.x + threadIdx.x;
    if (e < NE) atomicAdd(&g_degf[load_idx(ei, (long long)NE + e)], 1.0f);
}

__global__ void k_zero_agg() {
    int i = blockIdx.x * blockDim.x + threadIdx.x;
    if (i < NN * D / 4)
        reinterpret_cast<float4*>(g_agg)[i] = make_float4(0.f, 0.f, 0.f, 0.f);
}

// One warp per edge: gather h[src] row (512B), reduce-add into agg[dst].
__global__ void k_scatter(const void* __restrict__ ei,
                          const float* __restrict__ h) {
    int w = (blockIdx.x * blockDim.x + threadIdx.x) >> 5;
    if (w >= NE) return;
    int lane = threadIdx.x & 31;
    int src = load_idx(ei, w);
    int dst = load_idx(ei, (long long)NE + w);
    float4 v = __ldg(reinterpret_cast<const float4*>(h + (size_t)src * D) + lane);
    float* ap = g_agg + (size_t)dst * D + (size_t)lane * 4;
    asm volatile("red.global.add.v4.f32 [%0], {%1, %2, %3, %4};"
                 :: "l"(ap), "f"(v.x), "f"(v.y), "f"(v.z), "f"(v.w)
                 : "memory");
}

// out[i,:] = (agg[i,:] - deg[i]*h[i,:]) @ W^T + deg[i]*b
// Tile: 128 rows x 128 cols (BN = full D_out), BK=16, 256 threads, 8x8 micro-tile.
__global__ __launch_bounds__(256)
void k_gemm(const float* __restrict__ h,
            const float* __restrict__ W,      // [D_out, D_in] row-major
            const float* __restrict__ bias,   // [D_out]
            float* __restrict__ out) {
    __shared__ float As[16][128];   // As[k][row] = agg - deg*h
    __shared__ float Bs[16][128];   // Bs[k][n]   = W[n][k]

    const int tid  = threadIdx.x;
    const int row0 = blockIdx.x * 128;
    const int tx   = tid & 15;      // col group
    const int ty   = tid >> 4;      // row group

    float acc[8][8];
    #pragma unroll
    for (int i = 0; i < 8; i++)
        #pragma unroll
        for (int j = 0; j < 8; j++) acc[i][j] = 0.0f;

    for (int k0 = 0; k0 < D; k0 += 16) {
        // ---- load A tile (with fused agg - deg*h) ----
        #pragma unroll
        for (int it = 0; it < 2; it++) {
            int idx = tid + it * 256;
            int r   = idx >> 2;            // 0..127
            int kq  = (idx & 3) * 4;       // 0,4,8,12
            int grow = row0 + r;
            float4 v = make_float4(0.f, 0.f, 0.f, 0.f);
            if (grow < NN) {
                float dg = g_degf[grow];
                float4 a4 = *reinterpret_cast<const float4*>(
                    g_agg + (size_t)grow * D + k0 + kq);
                float4 h4 = __ldg(reinterpret_cast<const float4*>(
                    h + (size_t)grow * D + k0 + kq));
                v = make_float4(a4.x - dg * h4.x, a4.y - dg * h4.y,
                                a4.z - dg * h4.z, a4.w - dg * h4.w);
            }
            As[kq + 0][r] = v.x;
            As[kq + 1][r] = v.y;
            As[kq + 2][r] = v.z;
            As[kq + 3][r] = v.w;
        }
        // ---- load B tile (transpose W on the fly) ----
        #pragma unroll
        for (int it = 0; it < 2; it++) {
            int idx = tid + it * 256;
            int n   = idx >> 2;            // 0..127
            int kq  = (idx & 3) * 4;
            float4 wv = __ldg(reinterpret_cast<const float4*>(
                W + (size_t)n * D + k0 + kq));
            Bs[kq + 0][n] = wv.x;
            Bs[kq + 1][n] = wv.y;
            Bs[kq + 2][n] = wv.z;
            Bs[kq + 3][n] = wv.w;
        }
        __syncthreads();

        #pragma unroll
        for (int kk = 0; kk < 16; kk++) {
            float a[8], bb[8];
            *reinterpret_cast<float4*>(a)      = *reinterpret_cast<const float4*>(&As[kk][ty * 8]);
            *reinterpret_cast<float4*>(a + 4)  = *reinterpret_cast<const float4*>(&As[kk][ty * 8 + 4]);
            *reinterpret_cast<float4*>(bb)     = *reinterpret_cast<const float4*>(&Bs[kk][tx * 8]);
            *reinterpret_cast<float4*>(bb + 4) = *reinterpret_cast<const float4*>(&Bs[kk][tx * 8 + 4]);
            #pragma unroll
            for (int i = 0; i < 8; i++)
                #pragma unroll
                for (int j = 0; j < 8; j++)
                    acc[i][j] += a[i] * bb[j];
        }
        __syncthreads();
    }

    // ---- epilogue: + deg[i]*b[n] ----
    #pragma unroll
    for (int i = 0; i < 8; i++) {
        int grow = row0 + ty * 8 + i;
        if (grow >= NN) continue;
        float dg = g_degf[grow];
        #pragma unroll
        for (int j = 0; j < 8; j += 4) {
            int col = tx * 8 + j;
            float4 o;
            o.x = acc[i][j + 0] + dg * __ldg(bias + col + 0);
            o.y = acc[i][j + 1] + dg * __ldg(bias + col + 1);
            o.z = acc[i][j + 2] + dg * __ldg(bias + col + 2);
            o.w = acc[i][j + 3] + dg * __ldg(bias + col + 3);
            *reinterpret_cast<float4*>(out + (size_t)grow * D + col) = o;
        }
    }
}

// ---------------------------------------------------------------------------
extern "C" void kernel_launch(void* const* d_in, const int* in_sizes, int n_in,
                              void* d_out, int out_size) {
    const float* x  = (const float*)d_in[0];
    const float* W1 = (const float*)d_in[1];
    const float* b1 = (const float*)d_in[2];
    const float* W2 = (const float*)d_in[3];
    const float* b2 = (const float*)d_in[4];
    const float* W3 = (const float*)d_in[5];
    const float* b3 = (const float*)d_in[6];
    const void*  ei = d_in[7];
    float* out = (float*)d_out;

    float *h1, *h2;
    cudaGetSymbolAddress((void**)&h1, g_h1);
    cudaGetSymbolAddress((void**)&h2, g_h2);

    const int ZB = 256;
    k_detect<<<1, 32>>>((const int*)ei);

    // degree (same edge_index for all 3 layers)
    k_zero_deg<<<(NN + ZB - 1) / ZB, ZB>>>();
    k_deg<<<(NE + ZB - 1) / ZB, ZB>>>(ei);

    const int scatter_blocks = (NE * 32 + 255) / 256;   // 1 warp per edge
    const int agg_blocks     = (NN * D / 4 + ZB - 1) / ZB;
    const int gemm_blocks    = (NN + 127) / 128;

    // layer 1: h1 = (agg(x) - deg*x) W1^T + deg*b1
    k_zero_agg<<<agg_blocks, ZB>>>();
    k_scatter<<<scatter_blocks, 256>>>(ei, x);
    k_gemm<<<gemm_blocks, 256>>>(x, W1, b1, h1);

    // layer 2
    k_zero_agg<<<agg_blocks, ZB>>>();
    k_scatter<<<scatter_blocks, 256>>>(ei, h1);
    k_gemm<<<gemm_blocks, 256>>>(h1, W2, b2, h2);

    // layer 3 -> d_out
    k_zero_agg<<<agg_blocks, ZB>>>();
    k_scatter<<<scatter_blocks, 256>>>(ei, h2);
    k_gemm<<<gemm_blocks, 256>>>(h2, W3, b3, out);
}